// round 13
// baseline (speedup 1.0000x reference)
#include <cuda_runtime.h>
#include <cstdint>

#define NH    16
#define DK    64
#define BATCH 2
#define SEQ   2048
#define DEMB  1024
#define MTOT  (BATCH*SEQ)   // 4096

// Scratch (allocation-free: device globals)
// g_Q/g_K/g_V hold tf32-PRE-ROUNDED floats; g_Q pre-scaled by 0.125*log2(e).
// g_C holds tf32-PRE-ROUNDED ctx. g_X / g_W* hold tf32-PRE-ROUNDED inputs.
__device__ float g_Q[BATCH*NH*SEQ*DK];
__device__ float g_K[BATCH*NH*SEQ*DK];
__device__ float g_V[BATCH*NH*SEQ*DK];
__device__ float g_C[MTOT*DEMB];         // ctx, [b,s,h,dk] == row-major [4096,1024]
__device__ float g_X [MTOT*DEMB];        // rounded n
__device__ float g_Wq[DEMB*DEMB];
__device__ float g_Wk[DEMB*DEMB];
__device__ float g_Wv[DEMB*DEMB];
__device__ float g_Wo[DEMB*DEMB];

// ---------------------------------------------------------------------------
// helpers
// ---------------------------------------------------------------------------
__device__ __forceinline__ uint32_t smem_u32(const void* p) {
    uint32_t a;
    asm("{ .reg .u64 t; cvta.to.shared.u64 t, %1; cvt.u32.u64 %0, t; }"
        : "=r"(a) : "l"(p));
    return a;
}
__device__ __forceinline__ void cp16(uint32_t dst, const void* src) {
    asm volatile("cp.async.cg.shared.global [%0], [%1], 16;"
                 :: "r"(dst), "l"(src) : "memory");
}
#define CP_COMMIT() asm volatile("cp.async.commit_group;" ::: "memory")
#define CP_WAIT(n)  asm volatile("cp.async.wait_group %0;" :: "n"(n) : "memory")

__device__ __forceinline__ float ex2f(float x) {
    float r; asm("ex2.approx.ftz.f32 %0, %1;" : "=f"(r) : "f"(x)); return r;
}
__device__ __forceinline__ uint32_t cvt_tf32(float x) {
    uint32_t r; asm("cvt.rna.tf32.f32 %0, %1;" : "=r"(r) : "f"(x)); return r;
}
__device__ __forceinline__ float rnd_tf32(float x) {
    return __uint_as_float(cvt_tf32(x));
}
__device__ __forceinline__ void mma_tf32(float* d, const uint32_t* a, const uint32_t* b) {
    asm volatile("mma.sync.aligned.m16n8k8.row.col.f32.tf32.tf32.f32 "
        "{%0,%1,%2,%3}, {%4,%5,%6,%7}, {%8,%9}, {%0,%1,%2,%3};"
        : "+f"(d[0]), "+f"(d[1]), "+f"(d[2]), "+f"(d[3])
        : "r"(a[0]), "r"(a[1]), "r"(a[2]), "r"(a[3]), "r"(b[0]), "r"(b[1]));
}
__device__ __forceinline__ uint32_t f2b(float x) { return __float_as_uint(x); }

// ---------------------------------------------------------------------------
// pre-pass: tf32-round src into dst (float4 grid-stride).  ~15us total for
// X + 4 weights; removes ALL cvt from GEMM mainloops (round-12 audit: cvts
// were ~40% of mainloop issue slots; tensor pinned at 43% because of them).
// ---------------------------------------------------------------------------
__global__ void __launch_bounds__(256) round_pre(const float* __restrict__ src,
                                                 float* __restrict__ dst, int n4)
{
    int i = blockIdx.x * blockDim.x + threadIdx.x;
    const int stride = gridDim.x * blockDim.x;
    for (; i < n4; i += stride) {
        float4 v = ((const float4*)src)[i];
        v.x = rnd_tf32(v.x);
        v.y = rnd_tf32(v.y);
        v.z = rnd_tf32(v.z);
        v.w = rnd_tf32(v.w);
        ((float4*)dst)[i] = v;
    }
}

// ===========================================================================
// tf32 mma.sync GEMM core: 128x128 tile, 256 thr / 8 warps, warp m32 x n64.
// Inputs PRE-ROUNDED -> fragment loads are raw bits (no cvt).
// ===========================================================================
#define GPAD 36
#define GSTAGE (2 * 128 * GPAD)
#define GSMEM  (2 * GSTAGE * 4)

#define STAGE_LOAD(cc, ss) do {                                              \
    _Pragma("unroll")                                                        \
    for (int i = 0; i < 8; i++) {                                            \
        int f   = tid + 256 * i;                                             \
        int isB = f >> 10;                                                   \
        int gi  = f & 1023;                                                  \
        int row = gi >> 3;                                                   \
        int cir = gi & 7;                                                    \
        const float* src = (isB ? Bm + (size_t)(n0 + row) * DEMB             \
                                : A  + (size_t)(m0 + row) * DEMB)            \
                           + (cc) * 32 + cir * 4;                            \
        uint32_t dst = sb + ((ss) * GSTAGE + isB * (128 * GPAD)              \
                             + row * GPAD) * 4 + cir * 16;                   \
        cp16(dst, src);                                                      \
    }                                                                        \
} while (0)

#define GEMM_BODY                                                            \
    STAGE_LOAD(0, 0); CP_COMMIT();                                           \
    STAGE_LOAD(1, 1); CP_COMMIT();                                           \
    float acc[2][8][4];                                                      \
    _Pragma("unroll")                                                        \
    for (int mi = 0; mi < 2; mi++)                                           \
        _Pragma("unroll")                                                    \
        for (int ni = 0; ni < 8; ni++)                                       \
            _Pragma("unroll")                                                \
            for (int j = 0; j < 4; j++) acc[mi][ni][j] = 0.f;                \
    const int r4 = lane >> 2;                                                \
    const int c4 = lane & 3;                                                 \
    for (int c = 0; c < 32; c++) {                                           \
        CP_WAIT(1);                                                          \
        __syncthreads();                                                     \
        const float* As = gs + (c & 1) * GSTAGE;                             \
        const float* Bs = As + 128 * GPAD;                                   \
        _Pragma("unroll")                                                    \
        for (int k8 = 0; k8 < 4; k8++) {                                     \
            const int kb = k8 * 8 + c4;                                      \
            uint32_t a[2][4], b[8][2];                                       \
            _Pragma("unroll")                                                \
            for (int mi = 0; mi < 2; mi++) {                                 \
                const int r = wm + mi * 16 + r4;                             \
                a[mi][0] = f2b(As[r * GPAD + kb]);                           \
                a[mi][1] = f2b(As[(r + 8) * GPAD + kb]);                     \
                a[mi][2] = f2b(As[r * GPAD + kb + 4]);                       \
                a[mi][3] = f2b(As[(r + 8) * GPAD + kb + 4]);                 \
            }                                                                \
            _Pragma("unroll")                                                \
            for (int ni = 0; ni < 8; ni++) {                                 \
                const int cn = wn + ni * 8 + r4;                             \
                b[ni][0] = f2b(Bs[cn * GPAD + kb]);                          \
                b[ni][1] = f2b(Bs[cn * GPAD + kb + 4]);                      \
            }                                                                \
            _Pragma("unroll")                                                \
            for (int mi = 0; mi < 2; mi++)                                   \
                _Pragma("unroll")                                            \
                for (int ni = 0; ni < 8; ni++)                               \
                    mma_tf32(acc[mi][ni], a[mi], b[ni]);                     \
        }                                                                    \
        __syncthreads();                                                     \
        if (c + 2 < 32) STAGE_LOAD(c + 2, c & 1);                            \
        CP_COMMIT();                                                         \
    }

// ---- fused QKV projection: grid (24, 32); mat = blockIdx.x>>3 -----------
__global__ void __launch_bounds__(256, 2) gemm_qkv(const float* __restrict__ A,
                                                   const float* __restrict__ Wq,
                                                   const float* __restrict__ Wk,
                                                   const float* __restrict__ Wv,
                                                   float* __restrict__ Cq,
                                                   float* __restrict__ Ck,
                                                   float* __restrict__ Cv,
                                                   float qscale)
{
    extern __shared__ float gs[];
    const int tid  = threadIdx.x;
    const int lane = tid & 31;
    const int wid  = tid >> 5;
    const int wm   = (wid & 3) * 32;
    const int wn   = (wid >> 2) * 64;
    const int m0   = blockIdx.y * 128;
    const int mat  = blockIdx.x >> 3;
    const int n0   = (blockIdx.x & 7) * 128;
    const uint32_t sb = smem_u32(gs);

    const float* Bm = (mat == 0) ? Wq : (mat == 1) ? Wk : Wv;
    float*       C  = (mat == 0) ? Cq : (mat == 1) ? Ck : Cv;
    const float  cscale = (mat == 0) ? qscale : 1.0f;

    GEMM_BODY

    const int c2 = (lane & 3) * 2;
#pragma unroll
    for (int mi = 0; mi < 2; mi++) {
#pragma unroll
        for (int ni = 0; ni < 8; ni++) {
            const int m = m0 + wm + mi * 16 + r4;
            const int n = n0 + wn + ni * 8 + c2;
#pragma unroll
            for (int half = 0; half < 2; half++) {
                const int mm = m + half * 8;
                float2 v = make_float2(rnd_tf32(acc[mi][ni][2*half]   * cscale),
                                       rnd_tf32(acc[mi][ni][2*half+1] * cscale));
                const int b  = mm >> 11;
                const int s  = mm & (SEQ - 1);
                const int h  = n >> 6;
                const int dk = n & 63;
                *(float2*)&C[(((size_t)(b * NH + h) * SEQ + s) << 6) + dk] = v;
            }
        }
    }
}

// ---- output projection: C row-major ---------------------------------------
__global__ void __launch_bounds__(256, 2) gemm_out(const float* __restrict__ A,
                                                   const float* __restrict__ Bm,
                                                   float* __restrict__ C)
{
    extern __shared__ float gs[];
    const int tid  = threadIdx.x;
    const int lane = tid & 31;
    const int wid  = tid >> 5;
    const int wm   = (wid & 3) * 32;
    const int wn   = (wid >> 2) * 64;
    const int m0   = blockIdx.y * 128;
    const int n0   = blockIdx.x * 128;
    const uint32_t sb = smem_u32(gs);

    GEMM_BODY

    const int c2 = (lane & 3) * 2;
#pragma unroll
    for (int mi = 0; mi < 2; mi++) {
#pragma unroll
        for (int ni = 0; ni < 8; ni++) {
            const int m = m0 + wm + mi * 16 + r4;
            const int n = n0 + wn + ni * 8 + c2;
#pragma unroll
            for (int half = 0; half < 2; half++) {
                const int mm = m + half * 8;
                *(float2*)&C[(size_t)mm * DEMB + n] =
                    make_float2(acc[mi][ni][2*half], acc[mi][ni][2*half+1]);
            }
        }
    }
}

// ===========================================================================
// Tensor-core attention (round-7 config, measured 272us).
// Only change: epilogue tf32-pre-rounds ctx so gemm_out loads raw bits.
// ===========================================================================
#define CLIP2 7.2134752044448169f            // 5 * log2(e)
#define PK 68
#define PV 72
#define PP 132
#define AOFF_Q  0
#define AOFF_K0 (128*PK)
#define AOFF_K1 (2*128*PK)
#define AOFF_V  (3*128*PK)
#define AOFF_P  (3*128*PK + 128*PV)
#define ATT_SMEM ((AOFF_P + 128*PP)*4)       // 208896 bytes

__global__ void __launch_bounds__(256, 1) attn_tc()
{
    extern __shared__ float smf[];
    const uint32_t sb = smem_u32(smf);
    const int tid  = threadIdx.x;
    const int wid  = tid >> 5;
    const int lane = tid & 31;
    const int g    = lane >> 2;
    const int tq   = lane & 3;
    const int mw   = wid & 3;
    const int kw   = wid >> 2;
    const int bh   = blockIdx.y;
    const int q0   = blockIdx.x << 7;

    const float* Qg = g_Q + (size_t)bh * (SEQ * DK) + (size_t)q0 * DK;
    const float* Kg = g_K + (size_t)bh * (SEQ * DK);
    const float* Vg = g_V + (size_t)bh * (SEQ * DK);

#pragma unroll
    for (int i = 0; i < 8; i++) {
        int f = tid + 256 * i;
        int r = f >> 4;
        int c = (f & 15) << 2;
        cp16(sb + (AOFF_Q  + r * PK + c) * 4, Qg + (size_t)r * DK + c);
        cp16(sb + (AOFF_K0 + r * PK + c) * 4, Kg + (size_t)r * DK + c);
    }
    CP_COMMIT();

    float acc[2][4][4];
#pragma unroll
    for (int mi = 0; mi < 2; mi++)
#pragma unroll
        for (int ni = 0; ni < 4; ni++)
#pragma unroll
            for (int j = 0; j < 4; j++) acc[mi][ni][j] = 0.f;
    float rs[4] = {0.f, 0.f, 0.f, 0.f};

    const float* Qw  = smf + AOFF_Q + (mw * 32) * PK;
    float*       Pw  = smf + AOFF_P + (mw * 32) * PP;
    const float* Vsm = smf + AOFF_V;

    for (int t = 0; t < SEQ / 128; t++) {
        const float* Vt = Vg + (size_t)(t << 7) * DK;
#pragma unroll
        for (int i = 0; i < 8; i++) {
            int f = tid + 256 * i;
            int r = f >> 4;
            int c = (f & 15) << 2;
            cp16(sb + (AOFF_V + r * PV + c) * 4, Vt + (size_t)r * DK + c);
        }
        CP_COMMIT();
        if (t + 1 < SEQ / 128) {
            const float* Kt = Kg + (size_t)((t + 1) << 7) * DK;
            const int ko = ((t + 1) & 1) ? AOFF_K1 : AOFF_K0;
#pragma unroll
            for (int i = 0; i < 8; i++) {
                int f = tid + 256 * i;
                int r = f >> 4;
                int c = (f & 15) << 2;
                cp16(sb + (ko + r * PK + c) * 4, Kt + (size_t)r * DK + c);
            }
        }
        CP_COMMIT();

        CP_WAIT(2);
        __syncthreads();

        const float* Kb = smf + ((t & 1) ? AOFF_K1 : AOFF_K0) + (kw * 64) * PK;

        float sc[2][8][4];
#pragma unroll
        for (int mi = 0; mi < 2; mi++)
#pragma unroll
            for (int ni = 0; ni < 8; ni++)
#pragma unroll
                for (int j = 0; j < 4; j++) sc[mi][ni][j] = 0.f;

#pragma unroll 2
        for (int k8 = 0; k8 < 8; k8++) {
            const int kc = tq + 8 * k8;
            uint32_t a[2][4];
#pragma unroll
            for (int mi = 0; mi < 2; mi++) {
                const float* Qr = Qw + (mi * 16 + g) * PK + kc;
                a[mi][0] = f2b(Qr[0]);
                a[mi][1] = f2b(Qr[8 * PK]);
                a[mi][2] = f2b(Qr[4]);
                a[mi][3] = f2b(Qr[8 * PK + 4]);
            }
#pragma unroll
            for (int ni = 0; ni < 8; ni++) {
                uint32_t b[2];
                const float* Kr = Kb + (8 * ni + g) * PK + kc;
                b[0] = f2b(Kr[0]);
                b[1] = f2b(Kr[4]);
                mma_tf32(sc[0][ni], a[0], b);
                mma_tf32(sc[1][ni], a[1], b);
            }
        }

#pragma unroll
        for (int mi = 0; mi < 2; mi++) {
            float* Pm = Pw + (mi * 16 + g) * PP + kw * 64 + 2 * tq;
#pragma unroll
            for (int ni = 0; ni < 8; ni++) {
                float e0 = rnd_tf32(ex2f(fminf(fmaxf(sc[mi][ni][0], -CLIP2), CLIP2)));
                float e1 = rnd_tf32(ex2f(fminf(fmaxf(sc[mi][ni][1], -CLIP2), CLIP2)));
                float e2 = rnd_tf32(ex2f(fminf(fmaxf(sc[mi][ni][2], -CLIP2), CLIP2)));
                float e3 = rnd_tf32(ex2f(fminf(fmaxf(sc[mi][ni][3], -CLIP2), CLIP2)));
                rs[2 * mi]     += e0 + e1;
                rs[2 * mi + 1] += e2 + e3;
                *(float2*)&Pm[ni * 8]          = make_float2(e0, e1);
                *(float2*)&Pm[ni * 8 + 8 * PP] = make_float2(e2, e3);
            }
        }

        CP_WAIT(1);
        __syncthreads();

        const int dcol = kw * 32;
#pragma unroll 2
        for (int k8 = 0; k8 < 16; k8++) {
            const int kp = tq + 8 * k8;
            uint32_t a[2][4];
#pragma unroll
            for (int mi = 0; mi < 2; mi++) {
                const float* Pr = Pw + (mi * 16 + g) * PP + kp;
                a[mi][0] = f2b(Pr[0]);
                a[mi][1] = f2b(Pr[8 * PP]);
                a[mi][2] = f2b(Pr[4]);
                a[mi][3] = f2b(Pr[8 * PP + 4]);
            }
#pragma unroll
            for (int ni = 0; ni < 4; ni++) {
                uint32_t b[2];
                b[0] = f2b(Vsm[kp * PV + dcol + 8 * ni + g]);
                b[1] = f2b(Vsm[(kp + 4) * PV + dcol + 8 * ni + g]);
                mma_tf32(acc[0][ni], a[0], b);
                mma_tf32(acc[1][ni], a[1], b);
            }
        }
        __syncthreads();
    }

#pragma unroll
    for (int j = 0; j < 4; j++) {
        rs[j] += __shfl_xor_sync(0xffffffffu, rs[j], 1);
        rs[j] += __shfl_xor_sync(0xffffffffu, rs[j], 2);
    }
    float* Rsum = smf + AOFF_P;
    if (tq == 0) {
        Rsum[kw * 128 + mw * 32 + g]          = rs[0];
        Rsum[kw * 128 + mw * 32 + g + 8]      = rs[1];
        Rsum[kw * 128 + mw * 32 + 16 + g]     = rs[2];
        Rsum[kw * 128 + mw * 32 + 16 + g + 8] = rs[3];
    }
    __syncthreads();

    const int bb = bh >> 4;
    const int h  = bh & 15;
#pragma unroll
    for (int mi = 0; mi < 2; mi++) {
        const int r0 = mw * 32 + mi * 16 + g;
        const float inv0 = 1.f / (Rsum[r0]     + Rsum[128 + r0]);
        const float inv1 = 1.f / (Rsum[r0 + 8] + Rsum[128 + r0 + 8]);
        float* C0 = g_C + (((size_t)(bb * SEQ + q0 + r0) * NH + h) << 6) + kw * 32;
        float* C1 = C0 + ((size_t)8 * NH << 6);
#pragma unroll
        for (int ni = 0; ni < 4; ni++) {
            // pre-round ctx so gemm_out's A fragments are raw bits
            *(float2*)&C0[ni * 8 + 2 * tq] = make_float2(rnd_tf32(acc[mi][ni][0] * inv0),
                                                         rnd_tf32(acc[mi][ni][1] * inv0));
            *(float2*)&C1[ni * 8 + 2 * tq] = make_float2(rnd_tf32(acc[mi][ni][2] * inv1),
                                                         rnd_tf32(acc[mi][ni][3] * inv1));
        }
    }
}

// ===========================================================================
extern "C" void kernel_launch(void* const* d_in, const int* in_sizes, int n_in,
                              void* d_out, int out_size)
{
    const float* X  = (const float*)d_in[0];
    const float* Wq = (const float*)d_in[1];
    const float* Wk = (const float*)d_in[2];
    const float* Wv = (const float*)d_in[3];
    const float* Wo = (const float*)d_in[4];
    float* out = (float*)d_out;

    float *pQ, *pK, *pV, *pC, *pX, *pWq, *pWk, *pWv, *pWo;
    cudaGetSymbolAddress((void**)&pQ,  g_Q);
    cudaGetSymbolAddress((void**)&pK,  g_K);
    cudaGetSymbolAddress((void**)&pV,  g_V);
    cudaGetSymbolAddress((void**)&pC,  g_C);
    cudaGetSymbolAddress((void**)&pX,  g_X);
    cudaGetSymbolAddress((void**)&pWq, g_Wq);
    cudaGetSymbolAddress((void**)&pWk, g_Wk);
    cudaGetSymbolAddress((void**)&pWv, g_Wv);
    cudaGetSymbolAddress((void**)&pWo, g_Wo);

    cudaFuncSetAttribute(gemm_qkv, cudaFuncAttributeMaxDynamicSharedMemorySize, GSMEM);
    cudaFuncSetAttribute(gemm_out, cudaFuncAttributeMaxDynamicSharedMemorySize, GSMEM);
    cudaFuncSetAttribute(attn_tc,  cudaFuncAttributeMaxDynamicSharedMemorySize, ATT_SMEM);

    // Pre-round all GEMM inputs to tf32 once (rna idempotent -> identical math)
    round_pre<<<1024, 256>>>(X,  pX,  MTOT * DEMB / 4);
    round_pre<<<512,  256>>>(Wq, pWq, DEMB * DEMB / 4);
    round_pre<<<512,  256>>>(Wk, pWk, DEMB * DEMB / 4);
    round_pre<<<512,  256>>>(Wv, pWv, DEMB * DEMB / 4);
    round_pre<<<512,  256>>>(Wo, pWo, DEMB * DEMB / 4);

    // Fused QKV: 768 CTAs, 256 thr, 2 CTAs/SM.
    // Q projection carries 1/sqrt(Dk) * log2(e) so attention can use ex2.
    gemm_qkv<<<dim3(24, MTOT / 128), 256, GSMEM>>>(pX, pWq, pWk, pWv, pQ, pK, pV,
                                                   0.18033688011112042592f);

    attn_tc<<<dim3(SEQ / 128, BATCH * NH), 256, ATT_SMEM>>>();

    gemm_out<<<dim3(DEMB / 128, MTOT / 128), 256, GSMEM>>>(pC, pWo, out);
}

// round 16
// speedup vs baseline: 1.0570x; 1.0570x over previous
#include <cuda_runtime.h>
#include <cstdint>

#define NH    16
#define DK    64
#define BATCH 2
#define SEQ   2048
#define DEMB  1024
#define MTOT  (BATCH*SEQ)   // 4096

// Scratch (allocation-free: device globals)
__device__ float g_Q[BATCH*NH*SEQ*DK];
__device__ float g_K[BATCH*NH*SEQ*DK];
__device__ float g_V[BATCH*NH*SEQ*DK];
__device__ float g_C[MTOT*DEMB];         // ctx, [b,s,h,dk] == row-major
__device__ float g_X [MTOT*DEMB];        // tf32-rounded n
__device__ float g_Wq[DEMB*DEMB];
__device__ float g_Wk[DEMB*DEMB];
__device__ float g_Wv[DEMB*DEMB];
__device__ float g_Wo[DEMB*DEMB];

// ---------------------------------------------------------------------------
// helpers
// ---------------------------------------------------------------------------
__device__ __forceinline__ uint32_t smem_u32(const void* p) {
    uint32_t a;
    asm("{ .reg .u64 t; cvta.to.shared.u64 t, %1; cvt.u32.u64 %0, t; }"
        : "=r"(a) : "l"(p));
    return a;
}
__device__ __forceinline__ void cp16(uint32_t dst, const void* src) {
    asm volatile("cp.async.cg.shared.global [%0], [%1], 16;"
                 :: "r"(dst), "l"(src) : "memory");
}
#define CP_COMMIT() asm volatile("cp.async.commit_group;" ::: "memory")
#define CP_WAIT(n)  asm volatile("cp.async.wait_group %0;" :: "n"(n) : "memory")

__device__ __forceinline__ float ex2f(float x) {
    float r; asm("ex2.approx.ftz.f32 %0, %1;" : "=f"(r) : "f"(x)); return r;
}
__device__ __forceinline__ uint32_t cvt_tf32(float x) {
    uint32_t r; asm("cvt.rna.tf32.f32 %0, %1;" : "=r"(r) : "f"(x)); return r;
}
__device__ __forceinline__ float rnd_tf32(float x) {
    return __uint_as_float(cvt_tf32(x));
}
__device__ __forceinline__ void mma_tf32(float* d, const uint32_t* a, const uint32_t* b) {
    asm volatile("mma.sync.aligned.m16n8k8.row.col.f32.tf32.tf32.f32 "
        "{%0,%1,%2,%3}, {%4,%5,%6,%7}, {%8,%9}, {%0,%1,%2,%3};"
        : "+f"(d[0]), "+f"(d[1]), "+f"(d[2]), "+f"(d[3])
        : "r"(a[0]), "r"(a[1]), "r"(a[2]), "r"(a[3]), "r"(b[0]), "r"(b[1]));
}
__device__ __forceinline__ uint32_t f2b(float x) { return __float_as_uint(x); }

// ---------------------------------------------------------------------------
// fused pre-pass: tf32-round X and all 4 weights in ONE launch.
// 1 float4 per thread (8192 CTAs x 256) -> no serialization, max MLP.
// (round-13: 5 serial launches at 746GB/s cost ~40us and ate the cvt win)
// ---------------------------------------------------------------------------
__global__ void __launch_bounds__(256) round_pre_all(
    const float4* __restrict__ X,  const float4* __restrict__ Wq,
    const float4* __restrict__ Wk, const float4* __restrict__ Wv,
    const float4* __restrict__ Wo,
    float4* __restrict__ oX,  float4* __restrict__ oWq,
    float4* __restrict__ oWk, float4* __restrict__ oWv,
    float4* __restrict__ oWo)
{
    const int i = blockIdx.x * 256 + threadIdx.x;   // 0 .. 2M-1 float4s
    const float4* s; float4* d; int k;
    if (i < (1 << 20)) { s = X; d = oX; k = i; }
    else {
        const int j = i - (1 << 20);
        const int sel = j >> 18;
        k = j & 0x3FFFF;
        s = (sel == 0) ? Wq : (sel == 1) ? Wk : (sel == 2) ? Wv : Wo;
        d = (sel == 0) ? oWq : (sel == 1) ? oWk : (sel == 2) ? oWv : oWo;
    }
    float4 v = s[k];
    v.x = rnd_tf32(v.x); v.y = rnd_tf32(v.y);
    v.z = rnd_tf32(v.z); v.w = rnd_tf32(v.w);
    d[k] = v;
}

// ===========================================================================
// tf32 mma.sync GEMM core (unchanged from round 13: pre-rounded inputs,
// raw-bit fragments, 256 thr / 8 warps, warp m32 x n64, 2 CTAs/SM).
// ===========================================================================
#define GPAD 36
#define GSTAGE (2 * 128 * GPAD)
#define GSMEM  (2 * GSTAGE * 4)

#define STAGE_LOAD(cc, ss) do {                                              \
    _Pragma("unroll")                                                        \
    for (int i = 0; i < 8; i++) {                                            \
        int f   = tid + 256 * i;                                             \
        int isB = f >> 10;                                                   \
        int gi  = f & 1023;                                                  \
        int row = gi >> 3;                                                   \
        int cir = gi & 7;                                                    \
        const float* src = (isB ? Bm + (size_t)(n0 + row) * DEMB             \
                                : A  + (size_t)(m0 + row) * DEMB)            \
                           + (cc) * 32 + cir * 4;                            \
        uint32_t dst = sb + ((ss) * GSTAGE + isB * (128 * GPAD)              \
                             + row * GPAD) * 4 + cir * 16;                   \
        cp16(dst, src);                                                      \
    }                                                                        \
} while (0)

#define GEMM_BODY                                                            \
    STAGE_LOAD(0, 0); CP_COMMIT();                                           \
    STAGE_LOAD(1, 1); CP_COMMIT();                                           \
    float acc[2][8][4];                                                      \
    _Pragma("unroll")                                                        \
    for (int mi = 0; mi < 2; mi++)                                           \
        _Pragma("unroll")                                                    \
        for (int ni = 0; ni < 8; ni++)                                       \
            _Pragma("unroll")                                                \
            for (int j = 0; j < 4; j++) acc[mi][ni][j] = 0.f;                \
    const int r4 = lane >> 2;                                                \
    const int c4 = lane & 3;                                                 \
    for (int c = 0; c < 32; c++) {                                           \
        CP_WAIT(1);                                                          \
        __syncthreads();                                                     \
        const float* As = gs + (c & 1) * GSTAGE;                             \
        const float* Bs = As + 128 * GPAD;                                   \
        _Pragma("unroll")                                                    \
        for (int k8 = 0; k8 < 4; k8++) {                                     \
            const int kb = k8 * 8 + c4;                                      \
            uint32_t a[2][4], b[8][2];                                       \
            _Pragma("unroll")                                                \
            for (int mi = 0; mi < 2; mi++) {                                 \
                const int r = wm + mi * 16 + r4;                             \
                a[mi][0] = f2b(As[r * GPAD + kb]);                           \
                a[mi][1] = f2b(As[(r + 8) * GPAD + kb]);                     \
                a[mi][2] = f2b(As[r * GPAD + kb + 4]);                       \
                a[mi][3] = f2b(As[(r + 8) * GPAD + kb + 4]);                 \
            }                                                                \
            _Pragma("unroll")                                                \
            for (int ni = 0; ni < 8; ni++) {                                 \
                const int cn = wn + ni * 8 + r4;                             \
                b[ni][0] = f2b(Bs[cn * GPAD + kb]);                          \
                b[ni][1] = f2b(Bs[cn * GPAD + kb + 4]);                      \
            }                                                                \
            _Pragma("unroll")                                                \
            for (int mi = 0; mi < 2; mi++)                                   \
                _Pragma("unroll")                                            \
                for (int ni = 0; ni < 8; ni++)                               \
                    mma_tf32(acc[mi][ni], a[mi], b[ni]);                     \
        }                                                                    \
        __syncthreads();                                                     \
        if (c + 2 < 32) STAGE_LOAD(c + 2, c & 1);                            \
        CP_COMMIT();                                                         \
    }

__global__ void __launch_bounds__(256, 2) gemm_qkv(const float* __restrict__ A,
                                                   const float* __restrict__ Wq,
                                                   const float* __restrict__ Wk,
                                                   const float* __restrict__ Wv,
                                                   float* __restrict__ Cq,
                                                   float* __restrict__ Ck,
                                                   float* __restrict__ Cv,
                                                   float qscale)
{
    extern __shared__ float gs[];
    const int tid  = threadIdx.x;
    const int lane = tid & 31;
    const int wid  = tid >> 5;
    const int wm   = (wid & 3) * 32;
    const int wn   = (wid >> 2) * 64;
    const int m0   = blockIdx.y * 128;
    const int mat  = blockIdx.x >> 3;
    const int n0   = (blockIdx.x & 7) * 128;
    const uint32_t sb = smem_u32(gs);

    const float* Bm = (mat == 0) ? Wq : (mat == 1) ? Wk : Wv;
    float*       C  = (mat == 0) ? Cq : (mat == 1) ? Ck : Cv;
    const float  cscale = (mat == 0) ? qscale : 1.0f;

    GEMM_BODY

    const int c2 = (lane & 3) * 2;
#pragma unroll
    for (int mi = 0; mi < 2; mi++) {
#pragma unroll
        for (int ni = 0; ni < 8; ni++) {
            const int m = m0 + wm + mi * 16 + r4;
            const int n = n0 + wn + ni * 8 + c2;
#pragma unroll
            for (int half = 0; half < 2; half++) {
                const int mm = m + half * 8;
                float2 v = make_float2(rnd_tf32(acc[mi][ni][2*half]   * cscale),
                                       rnd_tf32(acc[mi][ni][2*half+1] * cscale));
                const int b  = mm >> 11;
                const int s  = mm & (SEQ - 1);
                const int h  = n >> 6;
                const int dk = n & 63;
                *(float2*)&C[(((size_t)(b * NH + h) * SEQ + s) << 6) + dk] = v;
            }
        }
    }
}

__global__ void __launch_bounds__(256, 2) gemm_out(const float* __restrict__ A,
                                                   const float* __restrict__ Bm,
                                                   float* __restrict__ C)
{
    extern __shared__ float gs[];
    const int tid  = threadIdx.x;
    const int lane = tid & 31;
    const int wid  = tid >> 5;
    const int wm   = (wid & 3) * 32;
    const int wn   = (wid >> 2) * 64;
    const int m0   = blockIdx.y * 128;
    const int n0   = blockIdx.x * 128;
    const uint32_t sb = smem_u32(gs);

    GEMM_BODY

    const int c2 = (lane & 3) * 2;
#pragma unroll
    for (int mi = 0; mi < 2; mi++) {
#pragma unroll
        for (int ni = 0; ni < 8; ni++) {
            const int m = m0 + wm + mi * 16 + r4;
            const int n = n0 + wn + ni * 8 + c2;
#pragma unroll
            for (int half = 0; half < 2; half++) {
                const int mm = m + half * 8;
                *(float2*)&C[(size_t)mm * DEMB + n] =
                    make_float2(acc[mi][ni][2*half], acc[mi][ni][2*half+1]);
            }
        }
    }
}

// ===========================================================================
// Tensor-core attention v4: q-tile 128, k-tile 64, smem 105.5KB -> 2 CTAs/SM.
// Round-7..13 were 1 CTA/SM at 2.5x above the crossbar floor (barrier/latency
// exposed, tensor 41%, issue 35%); two INDEPENDENT CTAs hide each other's
// stalls without raising per-warp LDS/mma (score 2.0, AV 2.0 LDS/mma).
// Pipelining via buffer lifetimes: K_{t+1} cp.async issued after score_t
// (overlaps AV_t), V_{t+1} after AV_t (overlaps score_{t+1}); 3 syncs/tile.
// Score: warp=(mw m32, kw 32-key half of 64). AV: warp=(mw, kw 32-d half).
// ===========================================================================
#define CLIP2 7.2134752044448169f            // 5 * log2(e)
#define NT (SEQ/64)                          // 32 k-tiles
#define PK  68
#define PV2 72
#define PP2 68
#define BOFF_Q  0                            // 128 x 68
#define BOFF_K  (128*PK)                     // 64 x 68
#define BOFF_V  (BOFF_K + 64*PK)             // 64 x 72
#define BOFF_P  (BOFF_V + 64*PV2)            // 128 x 68
#define ATT_SMEM ((BOFF_P + 128*PP2)*4)      // 105472 bytes

__global__ void __launch_bounds__(256, 2) attn_tc()
{
    extern __shared__ float smf[];
    const uint32_t sb = smem_u32(smf);
    const int tid  = threadIdx.x;
    const int wid  = tid >> 5;
    const int lane = tid & 31;
    const int g    = lane >> 2;
    const int tq   = lane & 3;
    const int mw   = wid & 3;          // m32 block
    const int kw   = wid >> 2;         // score: 32-key half | AV: 32-d half
    const int bh   = blockIdx.y;
    const int q0   = blockIdx.x << 7;

    const float* Qg = g_Q + (size_t)bh * (SEQ * DK) + (size_t)q0 * DK;
    const float* Kg = g_K + (size_t)bh * (SEQ * DK);
    const float* Vg = g_V + (size_t)bh * (SEQ * DK);

    // prologue: Q (2048 f4) + K0 (1024 f4) as group, then V0 (1024 f4)
#pragma unroll
    for (int i = 0; i < 8; i++) {
        int f = tid + 256 * i;
        int r = f >> 4;
        int c = (f & 15) << 2;
        cp16(sb + (BOFF_Q + r * PK + c) * 4, Qg + (size_t)r * DK + c);
    }
#pragma unroll
    for (int i = 0; i < 4; i++) {
        int f = tid + 256 * i;
        int r = f >> 4;
        int c = (f & 15) << 2;
        cp16(sb + (BOFF_K + r * PK + c) * 4, Kg + (size_t)r * DK + c);
    }
    CP_COMMIT();
#pragma unroll
    for (int i = 0; i < 4; i++) {
        int f = tid + 256 * i;
        int r = f >> 4;
        int c = (f & 15) << 2;
        cp16(sb + (BOFF_V + r * PV2 + c) * 4, Vg + (size_t)r * DK + c);
    }
    CP_COMMIT();

    float acc[2][4][4];
#pragma unroll
    for (int mi = 0; mi < 2; mi++)
#pragma unroll
        for (int ni = 0; ni < 4; ni++)
#pragma unroll
            for (int j = 0; j < 4; j++) acc[mi][ni][j] = 0.f;
    float rs[4] = {0.f, 0.f, 0.f, 0.f};

    const float* Qw = smf + BOFF_Q + (mw * 32) * PK;
    const float* Ks = smf + BOFF_K + (kw * 32) * PK;   // this warp's key half
    const float* Vs = smf + BOFF_V;
    float*       Pw = smf + BOFF_P + (mw * 32) * PP2;

    for (int t = 0; t < NT; t++) {
        CP_WAIT(1);                 // K_t complete (V_t may be in flight)
        __syncthreads();            // K_t visible; P buffer free (prev AV done)

        // ---- scores: 2 m16 x 4 n8 x 8 k8 (d = 64) ----
        float sc[2][4][4];
#pragma unroll
        for (int mi = 0; mi < 2; mi++)
#pragma unroll
            for (int ni = 0; ni < 4; ni++)
#pragma unroll
                for (int j = 0; j < 4; j++) sc[mi][ni][j] = 0.f;

#pragma unroll 2
        for (int k8 = 0; k8 < 8; k8++) {
            const int kc = tq + 8 * k8;
            uint32_t a[2][4];
#pragma unroll
            for (int mi = 0; mi < 2; mi++) {
                const float* Qr = Qw + (mi * 16 + g) * PK + kc;
                a[mi][0] = f2b(Qr[0]);
                a[mi][1] = f2b(Qr[8 * PK]);
                a[mi][2] = f2b(Qr[4]);
                a[mi][3] = f2b(Qr[8 * PK + 4]);
            }
#pragma unroll
            for (int ni = 0; ni < 4; ni++) {
                uint32_t b[2];
                const float* Kr = Ks + (8 * ni + g) * PK + kc;
                b[0] = f2b(Kr[0]);
                b[1] = f2b(Kr[4]);
                mma_tf32(sc[0][ni], a[0], b);
                mma_tf32(sc[1][ni], a[1], b);
            }
        }

        // ---- clip + 2^x + round, stage P cols [kw*32, kw*32+32) ----
#pragma unroll
        for (int mi = 0; mi < 2; mi++) {
            float* Pm = Pw + (mi * 16 + g) * PP2 + kw * 32 + 2 * tq;
#pragma unroll
            for (int ni = 0; ni < 4; ni++) {
                float e0 = rnd_tf32(ex2f(fminf(fmaxf(sc[mi][ni][0], -CLIP2), CLIP2)));
                float e1 = rnd_tf32(ex2f(fminf(fmaxf(sc[mi][ni][1], -CLIP2), CLIP2)));
                float e2 = rnd_tf32(ex2f(fminf(fmaxf(sc[mi][ni][2], -CLIP2), CLIP2)));
                float e3 = rnd_tf32(ex2f(fminf(fmaxf(sc[mi][ni][3], -CLIP2), CLIP2)));
                rs[2 * mi]     += e0 + e1;
                rs[2 * mi + 1] += e2 + e3;
                *(float2*)&Pm[ni * 8]           = make_float2(e0, e1);
                *(float2*)&Pm[ni * 8 + 8 * PP2] = make_float2(e2, e3);
            }
        }

        CP_WAIT(0);                 // V_t complete
        __syncthreads();            // V_t + all P halves visible; K_t consumed

        // K_{t+1} load overlaps AV_t
        if (t + 1 < NT) {
            const float* Kt = Kg + (size_t)((t + 1) << 6) * DK;
#pragma unroll
            for (int i = 0; i < 4; i++) {
                int f = tid + 256 * i;
                int r = f >> 4;
                int c = (f & 15) << 2;
                cp16(sb + (BOFF_K + r * PK + c) * 4, Kt + (size_t)r * DK + c);
            }
        }
        CP_COMMIT();

        // ---- AV: 2 m16 x 4 n8 (32-d half kw) x 8 k8 (64 keys) ----
        const int dcol = kw * 32;
#pragma unroll 2
        for (int k8 = 0; k8 < 8; k8++) {
            const int kp = tq + 8 * k8;
            uint32_t a[2][4];
#pragma unroll
            for (int mi = 0; mi < 2; mi++) {
                const float* Pr = Pw + (mi * 16 + g) * PP2 + kp;
                a[mi][0] = f2b(Pr[0]);
                a[mi][1] = f2b(Pr[8 * PP2]);
                a[mi][2] = f2b(Pr[4]);
                a[mi][3] = f2b(Pr[8 * PP2 + 4]);
            }
#pragma unroll
            for (int ni = 0; ni < 4; ni++) {
                uint32_t b[2];
                b[0] = f2b(Vs[kp * PV2 + dcol + 8 * ni + g]);
                b[1] = f2b(Vs[(kp + 4) * PV2 + dcol + 8 * ni + g]);
                mma_tf32(acc[0][ni], a[0], b);
                mma_tf32(acc[1][ni], a[1], b);
            }
        }
        __syncthreads();            // V_t consumed by all; P_t consumed

        // V_{t+1} load overlaps score_{t+1}
        if (t + 1 < NT) {
            const float* Vt = Vg + (size_t)((t + 1) << 6) * DK;
#pragma unroll
            for (int i = 0; i < 4; i++) {
                int f = tid + 256 * i;
                int r = f >> 4;
                int c = (f & 15) << 2;
                cp16(sb + (BOFF_V + r * PV2 + c) * 4, Vt + (size_t)r * DK + c);
            }
        }
        CP_COMMIT();
    }

    // ---- rsum: quad reduce, combine the two kw halves via smem ----
#pragma unroll
    for (int j = 0; j < 4; j++) {
        rs[j] += __shfl_xor_sync(0xffffffffu, rs[j], 1);
        rs[j] += __shfl_xor_sync(0xffffffffu, rs[j], 2);
    }
    float* Rsum = smf + BOFF_P;     // P free
    if (tq == 0) {
        Rsum[kw * 128 + mw * 32 + g]          = rs[0];
        Rsum[kw * 128 + mw * 32 + g + 8]      = rs[1];
        Rsum[kw * 128 + mw * 32 + 16 + g]     = rs[2];
        Rsum[kw * 128 + mw * 32 + 16 + g + 8] = rs[3];
    }
    __syncthreads();

    const int bb = bh >> 4;
    const int h  = bh & 15;
#pragma unroll
    for (int mi = 0; mi < 2; mi++) {
        const int r0 = mw * 32 + mi * 16 + g;
        const float inv0 = 1.f / (Rsum[r0]     + Rsum[128 + r0]);
        const float inv1 = 1.f / (Rsum[r0 + 8] + Rsum[128 + r0 + 8]);
        float* C0 = g_C + (((size_t)(bb * SEQ + q0 + r0) * NH + h) << 6) + kw * 32;
        float* C1 = C0 + ((size_t)8 * NH << 6);
#pragma unroll
        for (int ni = 0; ni < 4; ni++) {
            *(float2*)&C0[ni * 8 + 2 * tq] = make_float2(rnd_tf32(acc[mi][ni][0] * inv0),
                                                         rnd_tf32(acc[mi][ni][1] * inv0));
            *(float2*)&C1[ni * 8 + 2 * tq] = make_float2(rnd_tf32(acc[mi][ni][2] * inv1),
                                                         rnd_tf32(acc[mi][ni][3] * inv1));
        }
    }
}

// ===========================================================================
extern "C" void kernel_launch(void* const* d_in, const int* in_sizes, int n_in,
                              void* d_out, int out_size)
{
    const float* X  = (const float*)d_in[0];
    const float* Wq = (const float*)d_in[1];
    const float* Wk = (const float*)d_in[2];
    const float* Wv = (const float*)d_in[3];
    const float* Wo = (const float*)d_in[4];
    float* out = (float*)d_out;

    float *pQ, *pK, *pV, *pC, *pX, *pWq, *pWk, *pWv, *pWo;
    cudaGetSymbolAddress((void**)&pQ,  g_Q);
    cudaGetSymbolAddress((void**)&pK,  g_K);
    cudaGetSymbolAddress((void**)&pV,  g_V);
    cudaGetSymbolAddress((void**)&pC,  g_C);
    cudaGetSymbolAddress((void**)&pX,  g_X);
    cudaGetSymbolAddress((void**)&pWq, g_Wq);
    cudaGetSymbolAddress((void**)&pWk, g_Wk);
    cudaGetSymbolAddress((void**)&pWv, g_Wv);
    cudaGetSymbolAddress((void**)&pWo, g_Wo);

    cudaFuncSetAttribute(gemm_qkv, cudaFuncAttributeMaxDynamicSharedMemorySize, GSMEM);
    cudaFuncSetAttribute(gemm_out, cudaFuncAttributeMaxDynamicSharedMemorySize, GSMEM);
    cudaFuncSetAttribute(attn_tc,  cudaFuncAttributeMaxDynamicSharedMemorySize, ATT_SMEM);

    // One fused pre-round pass (X + 4 weights, 2M float4s, 1 per thread)
    round_pre_all<<<8192, 256>>>((const float4*)X,  (const float4*)Wq,
                                 (const float4*)Wk, (const float4*)Wv,
                                 (const float4*)Wo,
                                 (float4*)pX,  (float4*)pWq, (float4*)pWk,
                                 (float4*)pWv, (float4*)pWo);

    gemm_qkv<<<dim3(24, MTOT / 128), 256, GSMEM>>>(pX, pWq, pWk, pWv, pQ, pK, pV,
                                                   0.18033688011112042592f);

    attn_tc<<<dim3(SEQ / 128, BATCH * NH), 256, ATT_SMEM>>>();

    gemm_out<<<dim3(DEMB / 128, MTOT / 128), 256, GSMEM>>>(pC, pWo, out);
}

// round 17
// speedup vs baseline: 1.0633x; 1.0059x over previous
#include <cuda_runtime.h>
#include <cstdint>

#define NH    16
#define DK    64
#define BATCH 2
#define SEQ   2048
#define DEMB  1024
#define MTOT  (BATCH*SEQ)   // 4096

// Scratch (allocation-free: device globals)
__device__ float g_Q[BATCH*NH*SEQ*DK];
__device__ float g_K[BATCH*NH*SEQ*DK];
__device__ float g_V[BATCH*NH*SEQ*DK];
__device__ float g_C[MTOT*DEMB];         // ctx, [b,s,h,dk] == row-major
__device__ float g_X [MTOT*DEMB];        // tf32-rounded n
__device__ float g_Wq[DEMB*DEMB];
__device__ float g_Wk[DEMB*DEMB];
__device__ float g_Wv[DEMB*DEMB];
__device__ float g_Wo[DEMB*DEMB];

// ---------------------------------------------------------------------------
// helpers
// ---------------------------------------------------------------------------
__device__ __forceinline__ uint32_t smem_u32(const void* p) {
    uint32_t a;
    asm("{ .reg .u64 t; cvta.to.shared.u64 t, %1; cvt.u32.u64 %0, t; }"
        : "=r"(a) : "l"(p));
    return a;
}
__device__ __forceinline__ void cp16(uint32_t dst, const void* src) {
    asm volatile("cp.async.cg.shared.global [%0], [%1], 16;"
                 :: "r"(dst), "l"(src) : "memory");
}
#define CP_COMMIT() asm volatile("cp.async.commit_group;" ::: "memory")
#define CP_WAIT(n)  asm volatile("cp.async.wait_group %0;" :: "n"(n) : "memory")

__device__ __forceinline__ float ex2f(float x) {
    float r; asm("ex2.approx.ftz.f32 %0, %1;" : "=f"(r) : "f"(x)); return r;
}
__device__ __forceinline__ uint32_t cvt_tf32(float x) {
    uint32_t r; asm("cvt.rna.tf32.f32 %0, %1;" : "=r"(r) : "f"(x)); return r;
}
__device__ __forceinline__ float rnd_tf32(float x) {
    return __uint_as_float(cvt_tf32(x));
}
__device__ __forceinline__ void mma_tf32(float* d, const uint32_t* a, const uint32_t* b) {
    asm volatile("mma.sync.aligned.m16n8k8.row.col.f32.tf32.tf32.f32 "
        "{%0,%1,%2,%3}, {%4,%5,%6,%7}, {%8,%9}, {%0,%1,%2,%3};"
        : "+f"(d[0]), "+f"(d[1]), "+f"(d[2]), "+f"(d[3])
        : "r"(a[0]), "r"(a[1]), "r"(a[2]), "r"(a[3]), "r"(b[0]), "r"(b[1]));
}
__device__ __forceinline__ uint32_t f2b(float x) { return __float_as_uint(x); }

// ---------------------------------------------------------------------------
// fused pre-pass: tf32-round X and all 4 weights in ONE launch (round-16 win)
// ---------------------------------------------------------------------------
__global__ void __launch_bounds__(256) round_pre_all(
    const float4* __restrict__ X,  const float4* __restrict__ Wq,
    const float4* __restrict__ Wk, const float4* __restrict__ Wv,
    const float4* __restrict__ Wo,
    float4* __restrict__ oX,  float4* __restrict__ oWq,
    float4* __restrict__ oWk, float4* __restrict__ oWv,
    float4* __restrict__ oWo)
{
    const int i = blockIdx.x * 256 + threadIdx.x;   // 0 .. 2M-1 float4s
    const float4* s; float4* d; int k;
    if (i < (1 << 20)) { s = X; d = oX; k = i; }
    else {
        const int j = i - (1 << 20);
        const int sel = j >> 18;
        k = j & 0x3FFFF;
        s = (sel == 0) ? Wq : (sel == 1) ? Wk : (sel == 2) ? Wv : Wo;
        d = (sel == 0) ? oWq : (sel == 1) ? oWk : (sel == 2) ? oWv : oWo;
    }
    float4 v = s[k];
    v.x = rnd_tf32(v.x); v.y = rnd_tf32(v.y);
    v.z = rnd_tf32(v.z); v.w = rnd_tf32(v.w);
    d[k] = v;
}

// ===========================================================================
// tf32 mma.sync GEMM core v3: 3-STAGE cp.async pipeline, ONE barrier/iter,
// load issued BEFORE compute (2 chunk-times of latency slack; round-16
// profile: fma/alu ~0 after cvt removal, tensor 43% / issue 22% -> the
// 2-stage wait->sync->compute->sync structure was the remaining binder).
// Stage residents {c, c+1 in-flight, c+2 writing} distinct mod 3; the single
// barrier protects overwrite of stage (c-1)%3; in-order group completion
// makes CP_WAIT(1) sufficient.
// ===========================================================================
#define GPAD 36
#define GSTAGE (2 * 128 * GPAD)          // floats per stage = 9216 (36.9KB)
#define GSMEM  (3 * GSTAGE * 4)          // 110592 B -> 2 CTAs/SM (221KB<227KB)

#define STAGE_LOAD(cc, ss) do {                                              \
    _Pragma("unroll")                                                        \
    for (int i = 0; i < 8; i++) {                                            \
        int f   = tid + 256 * i;                                             \
        int isB = f >> 10;                                                   \
        int gi  = f & 1023;                                                  \
        int row = gi >> 3;                                                   \
        int cir = gi & 7;                                                    \
        const float* src = (isB ? Bm + (size_t)(n0 + row) * DEMB             \
                                : A  + (size_t)(m0 + row) * DEMB)            \
                           + (cc) * 32 + cir * 4;                            \
        uint32_t dst = sb + ((ss) * GSTAGE + isB * (128 * GPAD)              \
                             + row * GPAD) * 4 + cir * 16;                   \
        cp16(dst, src);                                                      \
    }                                                                        \
} while (0)

#define GEMM_BODY                                                            \
    STAGE_LOAD(0, 0); CP_COMMIT();                                           \
    STAGE_LOAD(1, 1); CP_COMMIT();                                           \
    float acc[2][8][4];                                                      \
    _Pragma("unroll")                                                        \
    for (int mi = 0; mi < 2; mi++)                                           \
        _Pragma("unroll")                                                    \
        for (int ni = 0; ni < 8; ni++)                                       \
            _Pragma("unroll")                                                \
            for (int j = 0; j < 4; j++) acc[mi][ni][j] = 0.f;                \
    const int r4 = lane >> 2;                                                \
    const int c4 = lane & 3;                                                 \
    for (int c = 0; c < 32; c++) {                                           \
        CP_WAIT(1);                                                          \
        __syncthreads();                                                     \
        if (c + 2 < 32) STAGE_LOAD(c + 2, (c + 2) % 3);                      \
        CP_COMMIT();                                                         \
        const float* As = gs + (c % 3) * GSTAGE;                             \
        const float* Bs = As + 128 * GPAD;                                   \
        _Pragma("unroll")                                                    \
        for (int k8 = 0; k8 < 4; k8++) {                                     \
            const int kb = k8 * 8 + c4;                                      \
            uint32_t a[2][4], b[8][2];                                       \
            _Pragma("unroll")                                                \
            for (int mi = 0; mi < 2; mi++) {                                 \
                const int r = wm + mi * 16 + r4;                             \
                a[mi][0] = f2b(As[r * GPAD + kb]);                           \
                a[mi][1] = f2b(As[(r + 8) * GPAD + kb]);                     \
                a[mi][2] = f2b(As[r * GPAD + kb + 4]);                       \
                a[mi][3] = f2b(As[(r + 8) * GPAD + kb + 4]);                 \
            }                                                                \
            _Pragma("unroll")                                                \
            for (int ni = 0; ni < 8; ni++) {                                 \
                const int cn = wn + ni * 8 + r4;                             \
                b[ni][0] = f2b(Bs[cn * GPAD + kb]);                          \
                b[ni][1] = f2b(Bs[cn * GPAD + kb + 4]);                      \
            }                                                                \
            _Pragma("unroll")                                                \
            for (int mi = 0; mi < 2; mi++)                                   \
                _Pragma("unroll")                                            \
                for (int ni = 0; ni < 8; ni++)                               \
                    mma_tf32(acc[mi][ni], a[mi], b[ni]);                     \
        }                                                                    \
    }

__global__ void __launch_bounds__(256, 2) gemm_qkv(const float* __restrict__ A,
                                                   const float* __restrict__ Wq,
                                                   const float* __restrict__ Wk,
                                                   const float* __restrict__ Wv,
                                                   float* __restrict__ Cq,
                                                   float* __restrict__ Ck,
                                                   float* __restrict__ Cv,
                                                   float qscale)
{
    extern __shared__ float gs[];
    const int tid  = threadIdx.x;
    const int lane = tid & 31;
    const int wid  = tid >> 5;
    const int wm   = (wid & 3) * 32;
    const int wn   = (wid >> 2) * 64;
    const int m0   = blockIdx.y * 128;
    const int mat  = blockIdx.x >> 3;
    const int n0   = (blockIdx.x & 7) * 128;
    const uint32_t sb = smem_u32(gs);

    const float* Bm = (mat == 0) ? Wq : (mat == 1) ? Wk : Wv;
    float*       C  = (mat == 0) ? Cq : (mat == 1) ? Ck : Cv;
    const float  cscale = (mat == 0) ? qscale : 1.0f;

    GEMM_BODY

    const int c2 = (lane & 3) * 2;
#pragma unroll
    for (int mi = 0; mi < 2; mi++) {
#pragma unroll
        for (int ni = 0; ni < 8; ni++) {
            const int m = m0 + wm + mi * 16 + r4;
            const int n = n0 + wn + ni * 8 + c2;
#pragma unroll
            for (int half = 0; half < 2; half++) {
                const int mm = m + half * 8;
                float2 v = make_float2(rnd_tf32(acc[mi][ni][2*half]   * cscale),
                                       rnd_tf32(acc[mi][ni][2*half+1] * cscale));
                const int b  = mm >> 11;
                const int s  = mm & (SEQ - 1);
                const int h  = n >> 6;
                const int dk = n & 63;
                *(float2*)&C[(((size_t)(b * NH + h) * SEQ + s) << 6) + dk] = v;
            }
        }
    }
}

__global__ void __launch_bounds__(256, 2) gemm_out(const float* __restrict__ A,
                                                   const float* __restrict__ Bm,
                                                   float* __restrict__ C)
{
    extern __shared__ float gs[];
    const int tid  = threadIdx.x;
    const int lane = tid & 31;
    const int wid  = tid >> 5;
    const int wm   = (wid & 3) * 32;
    const int wn   = (wid >> 2) * 64;
    const int m0   = blockIdx.y * 128;
    const int n0   = blockIdx.x * 128;
    const uint32_t sb = smem_u32(gs);

    GEMM_BODY

    const int c2 = (lane & 3) * 2;
#pragma unroll
    for (int mi = 0; mi < 2; mi++) {
#pragma unroll
        for (int ni = 0; ni < 8; ni++) {
            const int m = m0 + wm + mi * 16 + r4;
            const int n = n0 + wn + ni * 8 + c2;
#pragma unroll
            for (int half = 0; half < 2; half++) {
                const int mm = m + half * 8;
                *(float2*)&C[(size_t)mm * DEMB + n] =
                    make_float2(acc[mi][ni][2*half], acc[mi][ni][2*half+1]);
            }
        }
    }
}

// ===========================================================================
// Tensor-core attention v4 (round-16 config, unchanged):
// q-tile 128, k-tile 64, smem 105.5KB -> 2 CTAs/SM.
// ===========================================================================
#define CLIP2 7.2134752044448169f            // 5 * log2(e)
#define NT (SEQ/64)                          // 32 k-tiles
#define PK  68
#define PV2 72
#define PP2 68
#define BOFF_Q  0                            // 128 x 68
#define BOFF_K  (128*PK)                     // 64 x 68
#define BOFF_V  (BOFF_K + 64*PK)             // 64 x 72
#define BOFF_P  (BOFF_V + 64*PV2)            // 128 x 68
#define ATT_SMEM ((BOFF_P + 128*PP2)*4)      // 105472 bytes

__global__ void __launch_bounds__(256, 2) attn_tc()
{
    extern __shared__ float smf[];
    const uint32_t sb = smem_u32(smf);
    const int tid  = threadIdx.x;
    const int wid  = tid >> 5;
    const int lane = tid & 31;
    const int g    = lane >> 2;
    const int tq   = lane & 3;
    const int mw   = wid & 3;          // m32 block
    const int kw   = wid >> 2;         // score: 32-key half | AV: 32-d half
    const int bh   = blockIdx.y;
    const int q0   = blockIdx.x << 7;

    const float* Qg = g_Q + (size_t)bh * (SEQ * DK) + (size_t)q0 * DK;
    const float* Kg = g_K + (size_t)bh * (SEQ * DK);
    const float* Vg = g_V + (size_t)bh * (SEQ * DK);

#pragma unroll
    for (int i = 0; i < 8; i++) {
        int f = tid + 256 * i;
        int r = f >> 4;
        int c = (f & 15) << 2;
        cp16(sb + (BOFF_Q + r * PK + c) * 4, Qg + (size_t)r * DK + c);
    }
#pragma unroll
    for (int i = 0; i < 4; i++) {
        int f = tid + 256 * i;
        int r = f >> 4;
        int c = (f & 15) << 2;
        cp16(sb + (BOFF_K + r * PK + c) * 4, Kg + (size_t)r * DK + c);
    }
    CP_COMMIT();
#pragma unroll
    for (int i = 0; i < 4; i++) {
        int f = tid + 256 * i;
        int r = f >> 4;
        int c = (f & 15) << 2;
        cp16(sb + (BOFF_V + r * PV2 + c) * 4, Vg + (size_t)r * DK + c);
    }
    CP_COMMIT();

    float acc[2][4][4];
#pragma unroll
    for (int mi = 0; mi < 2; mi++)
#pragma unroll
        for (int ni = 0; ni < 4; ni++)
#pragma unroll
            for (int j = 0; j < 4; j++) acc[mi][ni][j] = 0.f;
    float rs[4] = {0.f, 0.f, 0.f, 0.f};

    const float* Qw = smf + BOFF_Q + (mw * 32) * PK;
    const float* Ks = smf + BOFF_K + (kw * 32) * PK;
    const float* Vs = smf + BOFF_V;
    float*       Pw = smf + BOFF_P + (mw * 32) * PP2;

    for (int t = 0; t < NT; t++) {
        CP_WAIT(1);
        __syncthreads();

        float sc[2][4][4];
#pragma unroll
        for (int mi = 0; mi < 2; mi++)
#pragma unroll
            for (int ni = 0; ni < 4; ni++)
#pragma unroll
                for (int j = 0; j < 4; j++) sc[mi][ni][j] = 0.f;

#pragma unroll 2
        for (int k8 = 0; k8 < 8; k8++) {
            const int kc = tq + 8 * k8;
            uint32_t a[2][4];
#pragma unroll
            for (int mi = 0; mi < 2; mi++) {
                const float* Qr = Qw + (mi * 16 + g) * PK + kc;
                a[mi][0] = f2b(Qr[0]);
                a[mi][1] = f2b(Qr[8 * PK]);
                a[mi][2] = f2b(Qr[4]);
                a[mi][3] = f2b(Qr[8 * PK + 4]);
            }
#pragma unroll
            for (int ni = 0; ni < 4; ni++) {
                uint32_t b[2];
                const float* Kr = Ks + (8 * ni + g) * PK + kc;
                b[0] = f2b(Kr[0]);
                b[1] = f2b(Kr[4]);
                mma_tf32(sc[0][ni], a[0], b);
                mma_tf32(sc[1][ni], a[1], b);
            }
        }

#pragma unroll
        for (int mi = 0; mi < 2; mi++) {
            float* Pm = Pw + (mi * 16 + g) * PP2 + kw * 32 + 2 * tq;
#pragma unroll
            for (int ni = 0; ni < 4; ni++) {
                float e0 = rnd_tf32(ex2f(fminf(fmaxf(sc[mi][ni][0], -CLIP2), CLIP2)));
                float e1 = rnd_tf32(ex2f(fminf(fmaxf(sc[mi][ni][1], -CLIP2), CLIP2)));
                float e2 = rnd_tf32(ex2f(fminf(fmaxf(sc[mi][ni][2], -CLIP2), CLIP2)));
                float e3 = rnd_tf32(ex2f(fminf(fmaxf(sc[mi][ni][3], -CLIP2), CLIP2)));
                rs[2 * mi]     += e0 + e1;
                rs[2 * mi + 1] += e2 + e3;
                *(float2*)&Pm[ni * 8]           = make_float2(e0, e1);
                *(float2*)&Pm[ni * 8 + 8 * PP2] = make_float2(e2, e3);
            }
        }

        CP_WAIT(0);
        __syncthreads();

        if (t + 1 < NT) {
            const float* Kt = Kg + (size_t)((t + 1) << 6) * DK;
#pragma unroll
            for (int i = 0; i < 4; i++) {
                int f = tid + 256 * i;
                int r = f >> 4;
                int c = (f & 15) << 2;
                cp16(sb + (BOFF_K + r * PK + c) * 4, Kt + (size_t)r * DK + c);
            }
        }
        CP_COMMIT();

        const int dcol = kw * 32;
#pragma unroll 2
        for (int k8 = 0; k8 < 8; k8++) {
            const int kp = tq + 8 * k8;
            uint32_t a[2][4];
#pragma unroll
            for (int mi = 0; mi < 2; mi++) {
                const float* Pr = Pw + (mi * 16 + g) * PP2 + kp;
                a[mi][0] = f2b(Pr[0]);
                a[mi][1] = f2b(Pr[8 * PP2]);
                a[mi][2] = f2b(Pr[4]);
                a[mi][3] = f2b(Pr[8 * PP2 + 4]);
            }
#pragma unroll
            for (int ni = 0; ni < 4; ni++) {
                uint32_t b[2];
                b[0] = f2b(Vs[kp * PV2 + dcol + 8 * ni + g]);
                b[1] = f2b(Vs[(kp + 4) * PV2 + dcol + 8 * ni + g]);
                mma_tf32(acc[0][ni], a[0], b);
                mma_tf32(acc[1][ni], a[1], b);
            }
        }
        __syncthreads();

        if (t + 1 < NT) {
            const float* Vt = Vg + (size_t)((t + 1) << 6) * DK;
#pragma unroll
            for (int i = 0; i < 4; i++) {
                int f = tid + 256 * i;
                int r = f >> 4;
                int c = (f & 15) << 2;
                cp16(sb + (BOFF_V + r * PV2 + c) * 4, Vt + (size_t)r * DK + c);
            }
        }
        CP_COMMIT();
    }

#pragma unroll
    for (int j = 0; j < 4; j++) {
        rs[j] += __shfl_xor_sync(0xffffffffu, rs[j], 1);
        rs[j] += __shfl_xor_sync(0xffffffffu, rs[j], 2);
    }
    float* Rsum = smf + BOFF_P;
    if (tq == 0) {
        Rsum[kw * 128 + mw * 32 + g]          = rs[0];
        Rsum[kw * 128 + mw * 32 + g + 8]      = rs[1];
        Rsum[kw * 128 + mw * 32 + 16 + g]     = rs[2];
        Rsum[kw * 128 + mw * 32 + 16 + g + 8] = rs[3];
    }
    __syncthreads();

    const int bb = bh >> 4;
    const int h  = bh & 15;
#pragma unroll
    for (int mi = 0; mi < 2; mi++) {
        const int r0 = mw * 32 + mi * 16 + g;
        const float inv0 = 1.f / (Rsum[r0]     + Rsum[128 + r0]);
        const float inv1 = 1.f / (Rsum[r0 + 8] + Rsum[128 + r0 + 8]);
        float* C0 = g_C + (((size_t)(bb * SEQ + q0 + r0) * NH + h) << 6) + kw * 32;
        float* C1 = C0 + ((size_t)8 * NH << 6);
#pragma unroll
        for (int ni = 0; ni < 4; ni++) {
            *(float2*)&C0[ni * 8 + 2 * tq] = make_float2(rnd_tf32(acc[mi][ni][0] * inv0),
                                                         rnd_tf32(acc[mi][ni][1] * inv0));
            *(float2*)&C1[ni * 8 + 2 * tq] = make_float2(rnd_tf32(acc[mi][ni][2] * inv1),
                                                         rnd_tf32(acc[mi][ni][3] * inv1));
        }
    }
}

// ===========================================================================
extern "C" void kernel_launch(void* const* d_in, const int* in_sizes, int n_in,
                              void* d_out, int out_size)
{
    const float* X  = (const float*)d_in[0];
    const float* Wq = (const float*)d_in[1];
    const float* Wk = (const float*)d_in[2];
    const float* Wv = (const float*)d_in[3];
    const float* Wo = (const float*)d_in[4];
    float* out = (float*)d_out;

    float *pQ, *pK, *pV, *pC, *pX, *pWq, *pWk, *pWv, *pWo;
    cudaGetSymbolAddress((void**)&pQ,  g_Q);
    cudaGetSymbolAddress((void**)&pK,  g_K);
    cudaGetSymbolAddress((void**)&pV,  g_V);
    cudaGetSymbolAddress((void**)&pC,  g_C);
    cudaGetSymbolAddress((void**)&pX,  g_X);
    cudaGetSymbolAddress((void**)&pWq, g_Wq);
    cudaGetSymbolAddress((void**)&pWk, g_Wk);
    cudaGetSymbolAddress((void**)&pWv, g_Wv);
    cudaGetSymbolAddress((void**)&pWo, g_Wo);

    cudaFuncSetAttribute(gemm_qkv, cudaFuncAttributeMaxDynamicSharedMemorySize, GSMEM);
    cudaFuncSetAttribute(gemm_out, cudaFuncAttributeMaxDynamicSharedMemorySize, GSMEM);
    cudaFuncSetAttribute(attn_tc,  cudaFuncAttributeMaxDynamicSharedMemorySize, ATT_SMEM);

    round_pre_all<<<8192, 256>>>((const float4*)X,  (const float4*)Wq,
                                 (const float4*)Wk, (const float4*)Wv,
                                 (const float4*)Wo,
                                 (float4*)pX,  (float4*)pWq, (float4*)pWk,
                                 (float4*)pWv, (float4*)pWo);

    gemm_qkv<<<dim3(24, MTOT / 128), 256, GSMEM>>>(pX, pWq, pWk, pWv, pQ, pK, pV,
                                                   0.18033688011112042592f);

    attn_tc<<<dim3(SEQ / 128, BATCH * NH), 256, ATT_SMEM>>>();

    gemm_out<<<dim3(DEMB / 128, MTOT / 128), 256, GSMEM>>>(pC, pWo, out);
}